// round 5
// baseline (speedup 1.0000x reference)
#include <cuda_runtime.h>
#include <math.h>

#define D_DIM   1024
#define E_DIM   64
#define TOPK    8
#define BM      128
#define BK      32
#define KCHUNK  256          // reference-matching accumulation chunk
#define NTHREADS 256

// scratch: global expert counters (allocation-free per harness rules)
__device__ int g_counts[E_DIM];

__device__ __forceinline__ unsigned long long pack2(float a, float b) {
    unsigned long long r;
    asm("mov.b64 %0, {%1, %2};" : "=l"(r) : "f"(a), "f"(b));
    return r;
}
__device__ __forceinline__ void fma2(unsigned long long& d,
                                     unsigned long long a,
                                     unsigned long long b) {
    // packed 2x fp32 FMA (per-lane IEEE fp32, 2x FFMA throughput)
    asm("fma.rn.f32x2 %0, %1, %2, %3;" : "=l"(d) : "l"(a), "l"(b), "l"(d));
}
__device__ __forceinline__ void add2(unsigned long long& d,
                                     unsigned long long a) {
    asm("add.rn.f32x2 %0, %0, %1;" : "+l"(d) : "l"(a));
}

__global__ void zero_counts_kernel() {
    if (threadIdx.x < E_DIM) g_counts[threadIdx.x] = 0;
}

__global__ __launch_bounds__(NTHREADS, 2)
void gate_kernel(const float* __restrict__ x, const float* __restrict__ W,
                 const float* __restrict__ b,
                 float* __restrict__ out_idx, float* __restrict__ out_gate) {
    // pool unions the GEMM staging tiles with the per-row logits buffer
    __shared__ __align__(16) float pool[BM * (E_DIM + 4)];
    __shared__ float bsh[E_DIM];
    __shared__ int hist[E_DIM];

    float* xs = pool;
    unsigned long long* ws2 = (unsigned long long*)(pool + BK * BM);

    const int tid = threadIdx.x;
    const int tx = tid & 15;   // expert group: experts tx*4..tx*4+3
    const int ty = tid >> 4;   // row group:    rows   ty*8..ty*8+7
    const int row0 = blockIdx.x * BM;

    if (tid < E_DIM) { bsh[tid] = b[tid]; hist[tid] = 0; }

    unsigned long long tot[4][4];   // running total: ((P0+P1)+P2)+P3
    unsigned long long acc[4][4];   // current 256-k chunk partial
#pragma unroll
    for (int p = 0; p < 4; p++)
#pragma unroll
        for (int e = 0; e < 4; e++) { tot[p][e] = 0ULL; acc[p][e] = 0ULL; }

    // k-chunked accumulation, emulating the reference GEMM's order:
    // each 256-chunk is a sequential fp32 FMA chain from zero; chunk
    // partials are folded left-to-right with single fp32 adds.
    for (int ch = 0; ch < D_DIM / KCHUNK; ch++) {
        for (int kc2 = 0; kc2 < KCHUNK; kc2 += BK) {
            const int kc = ch * KCHUNK + kc2;
            __syncthreads();
            // ---- load x tile, transposed to k-major: xs[k][row] ----
#pragma unroll
            for (int it = 0; it < 4; it++) {
                int i = tid + it * NTHREADS;
                int r = i >> 3, f4 = (i & 7) << 2;
                float4 v = *(const float4*)(x + (size_t)(row0 + r) * D_DIM + kc + f4);
                xs[(f4 + 0) * BM + r] = v.x;
                xs[(f4 + 1) * BM + r] = v.y;
                xs[(f4 + 2) * BM + r] = v.z;
                xs[(f4 + 3) * BM + r] = v.w;
            }
            // ---- load W tile as pre-broadcast (w,w) u64 pairs ----
#pragma unroll
            for (int it = 0; it < 2; it++) {
                int i = tid + it * NTHREADS;
                int e = i >> 3, f4 = (i & 7) << 2;
                float4 v = *(const float4*)(W + (size_t)e * D_DIM + kc + f4);
                ws2[(f4 + 0) * E_DIM + e] = pack2(v.x, v.x);
                ws2[(f4 + 1) * E_DIM + e] = pack2(v.y, v.y);
                ws2[(f4 + 2) * E_DIM + e] = pack2(v.z, v.z);
                ws2[(f4 + 3) * E_DIM + e] = pack2(v.w, v.w);
            }
            __syncthreads();
            // ---- mainloop: 4x LDS.128 + 16x FFMA2 per k ----
#pragma unroll
            for (int k = 0; k < BK; k++) {
                const ulonglong2* xr = (const ulonglong2*)(xs + k * BM + ty * 8);
                ulonglong2 xa = xr[0], xb = xr[1];
                const ulonglong2* wr = (const ulonglong2*)(ws2 + k * E_DIM + tx * 4);
                ulonglong2 wa = wr[0], wb = wr[1];
                fma2(acc[0][0], xa.x, wa.x); fma2(acc[0][1], xa.x, wa.y);
                fma2(acc[0][2], xa.x, wb.x); fma2(acc[0][3], xa.x, wb.y);
                fma2(acc[1][0], xa.y, wa.x); fma2(acc[1][1], xa.y, wa.y);
                fma2(acc[1][2], xa.y, wb.x); fma2(acc[1][3], xa.y, wb.y);
                fma2(acc[2][0], xb.x, wa.x); fma2(acc[2][1], xb.x, wa.y);
                fma2(acc[2][2], xb.x, wb.x); fma2(acc[2][3], xb.x, wb.y);
                fma2(acc[3][0], xb.y, wa.x); fma2(acc[3][1], xb.y, wa.y);
                fma2(acc[3][2], xb.y, wb.x); fma2(acc[3][3], xb.y, wb.y);
            }
        }
        // ---- fold chunk partial into running total (1 fp32 add/lane) ----
#pragma unroll
        for (int p = 0; p < 4; p++)
#pragma unroll
            for (int e = 0; e < 4; e++) { add2(tot[p][e], acc[p][e]); acc[p][e] = 0ULL; }
    }
    __syncthreads();

    // ---- epilogue: spill biased logits to smem, padded stride E+4 ----
    float* Ls = pool;
#pragma unroll
    for (int p = 0; p < 4; p++) {
        int r0 = ty * 8 + p * 2;
#pragma unroll
        for (int e = 0; e < 4; e++) {
            int ec = tx * 4 + e;
            float lo = __uint_as_float((unsigned)(tot[p][e] & 0xffffffffULL));
            float hi = __uint_as_float((unsigned)(tot[p][e] >> 32));
            Ls[(size_t)r0 * (E_DIM + 4) + ec]       = lo + bsh[ec];
            Ls[(size_t)(r0 + 1) * (E_DIM + 4) + ec] = hi + bsh[ec];
        }
    }
    __syncthreads();

    if (tid < BM) {
        const int row = row0 + tid;
        float* L = Ls + (size_t)tid * (E_DIM + 4);
        float mx = L[0];
#pragma unroll
        for (int e = 1; e < E_DIM; e++) mx = fmaxf(mx, L[e]);
        float s = 0.f;
#pragma unroll
        for (int e = 0; e < E_DIM; e++) s += expf(L[e] - mx);
        float inv = 1.f / s;
        // top-8 by raw logits (monotone surrogate for softmax order).
        // Strict >, lowest index wins ties (matches lax.top_k).
        const float NEG_INF = __int_as_float(0xff800000);
        unsigned long long used = 0ULL;
        float gv[TOPK]; int gi[TOPK];
        float gs = 0.f;
#pragma unroll
        for (int j = 0; j < TOPK; j++) {
            float best = NEG_INF; int bi = 0;
            for (int e = 0; e < E_DIM; e++) {
                float v = L[e];
                if (!((used >> e) & 1ULL) && v > best) { best = v; bi = e; }
            }
            used |= (1ULL << bi);
            float g = expf(best - mx) * inv;
            gv[j] = g; gi[j] = bi; gs += g;
            atomicAdd(&hist[bi], 1);
        }
        float rn = 1.f / (gs + 1e-8f);
#pragma unroll
        for (int j = 0; j < TOPK; j++) {
            out_idx[(size_t)row * TOPK + j]  = (float)gi[j];
            out_gate[(size_t)row * TOPK + j] = gv[j] * rn;
        }
    }
    __syncthreads();
    if (tid < E_DIM) atomicAdd(&g_counts[tid], hist[tid]);
}

__global__ void var_finish_kernel(const float* __restrict__ eu,
                                  float* __restrict__ outv, float invN) {
    if (threadIdx.x == 0) {
        float u[E_DIM];
        float m = 0.f;
        for (int e = 0; e < E_DIM; e++) {
            u[e] = 0.95f * eu[e] + 0.05f * ((float)g_counts[e] * invN);
            m += u[e];
        }
        m *= (1.f / E_DIM);
        float v = 0.f;
        for (int e = 0; e < E_DIM; e++) {
            float d = u[e] - m;
            v += d * d;
        }
        *outv = v * (1.f / (E_DIM - 1));   // ddof=1
    }
}

extern "C" void kernel_launch(void* const* d_in, const int* in_sizes, int n_in,
                              void* d_out, int out_size) {
    const float* x  = (const float*)d_in[0];
    const float* W  = (const float*)d_in[1];
    const float* b  = (const float*)d_in[2];
    const float* eu = (const float*)d_in[3];
    const int N = in_sizes[0] / D_DIM;   // 262144

    float* out      = (float*)d_out;
    float* out_idx  = out;                         // [N,8] indices (as float)
    float* out_gate = out + (size_t)N * TOPK;      // [N,8] gates
    float* out_var  = out + (out_size - 1);        // scalar variance

    zero_counts_kernel<<<1, 64>>>();
    gate_kernel<<<N / BM, NTHREADS>>>(x, W, b, out_idx, out_gate);
    var_finish_kernel<<<1, 32>>>(eu, out_var, 1.f / (float)N);
}

// round 6
// speedup vs baseline: 1.4654x; 1.4654x over previous
#include <cuda_runtime.h>
#include <math.h>

#define D_DIM   1024
#define E_DIM   64
#define TOPK    8
#define BM      128
#define BK      32
#define NTHREADS 256
#define XS_STRIDE 33     // conflict-free scalar store/read for x tile
#define LS_STRIDE 68

// global scratch (allocation-free per harness rules)
__device__ int   g_counts[E_DIM];
__device__ int   g_done;
__device__ float Wt[D_DIM * E_DIM];   // W transposed: Wt[k][e]

__device__ __forceinline__ unsigned long long pack2(float a, float b) {
    unsigned long long r;
    asm("mov.b64 %0, {%1, %2};" : "=l"(r) : "f"(a), "f"(b));
    return r;
}
__device__ __forceinline__ void fma2(unsigned long long& d,
                                     unsigned long long a,
                                     unsigned long long b) {
    // packed 2x fp32 FMA (per-lane IEEE fp32) -- same math as scalar FFMA
    asm("fma.rn.f32x2 %0, %1, %2, %3;" : "=l"(d) : "l"(a), "l"(b), "l"(d));
}
__device__ __forceinline__ void add2(unsigned long long& d,
                                     unsigned long long a) {
    asm("add.rn.f32x2 %0, %0, %1;" : "+l"(d) : "l"(a));
}

// One-shot (per launch) W transpose: read coalesced along k, write [k][e].
__global__ void transpose_w_kernel(const float* __restrict__ W) {
    int idx = blockIdx.x * blockDim.x + threadIdx.x;   // = e*D + k
    int e = idx >> 10, k = idx & (D_DIM - 1);
    Wt[k * E_DIM + e] = W[idx];
}

__global__ __launch_bounds__(NTHREADS, 2)
void gate_kernel(const float* __restrict__ x, const float* __restrict__ b,
                 const float* __restrict__ eu,
                 float* __restrict__ out_idx, float* __restrict__ out_gate,
                 float* __restrict__ out_var, float invN) {
    // pool unions {xs + ws} (mainloop) with Ls (epilogue logits)
    //   xs: [BM][XS_STRIDE] floats = 4224
    //   ws: [BK][E]         floats = 2048   (total 6272)
    //   Ls: [BM][LS_STRIDE] floats = 8704   (pool size)
    __shared__ __align__(16) float pool[BM * LS_STRIDE];
    __shared__ float bsh[E_DIM];
    __shared__ int hist[E_DIM];
    __shared__ int lastFlag;

    float* xs = pool;                       // row-major [row][k], stride 33
    float* ws = pool + BM * XS_STRIDE;      // [k][e], natural expert pairs

    const int tid = threadIdx.x;
    const int tx = tid & 7;      // expert group: experts tx*8 .. tx*8+7
    const int ty = tid >> 3;     // row group:    rows    ty*4 .. ty*4+3
    const int row0 = blockIdx.x * BM;

    if (tid < E_DIM) { bsh[tid] = b[tid]; hist[tid] = 0; }

    unsigned long long acc[4][4];  // [row][expert-pair] current 256-chunk
    unsigned long long tot[4][4];  // running total ((P0+P1)+P2)+P3
#pragma unroll
    for (int r = 0; r < 4; r++)
#pragma unroll
        for (int e = 0; e < 4; e++) { acc[r][e] = 0ULL; tot[r][e] = 0ULL; }

    const int xr = tid >> 3;          // base row for staging (+32 per it)
    const int xf = (tid & 7) << 2;    // k-offset within tile

    float4 xp[4], wp[2];              // prefetch registers
    // prefetch tile 0
    {
#pragma unroll
        for (int it2 = 0; it2 < 4; it2++)
            xp[it2] = *(const float4*)(x + (size_t)(row0 + xr + it2 * 32) * D_DIM + xf);
#pragma unroll
        for (int it2 = 0; it2 < 2; it2++)
            wp[it2] = *(const float4*)(Wt + (tid + it2 * NTHREADS) * 4);
    }

    for (int ch = 0; ch < 4; ch++) {          // 4 chunks of 256 k
#pragma unroll 1
        for (int sub = 0; sub < 8; sub++) {   // 8 BK-tiles per chunk
            const int it = ch * 8 + sub;
            __syncthreads();   // previous tile's consumers done
            // ---- store staged tile to smem (conflict-free patterns) ----
#pragma unroll
            for (int it2 = 0; it2 < 4; it2++) {
                float* dst = xs + (size_t)(xr + it2 * 32) * XS_STRIDE + xf;
                dst[0] = xp[it2].x; dst[1] = xp[it2].y;
                dst[2] = xp[it2].z; dst[3] = xp[it2].w;
            }
#pragma unroll
            for (int it2 = 0; it2 < 2; it2++)
                *(float4*)(ws + (tid + it2 * NTHREADS) * 4) = wp[it2];
            __syncthreads();
            // ---- prefetch next tile while computing this one ----
            if (it < 31) {
                const int kn = (it + 1) * BK;
#pragma unroll
                for (int it2 = 0; it2 < 4; it2++)
                    xp[it2] = *(const float4*)(x + (size_t)(row0 + xr + it2 * 32) * D_DIM + kn + xf);
#pragma unroll
                for (int it2 = 0; it2 < 2; it2++)
                    wp[it2] = *(const float4*)(Wt + (size_t)kn * E_DIM + (tid + it2 * NTHREADS) * 4);
            }
            // ---- mainloop: per k: 4 LDS.32(x) + 2 LDS.128(w) + 16 FFMA2 ----
#pragma unroll
            for (int k = 0; k < BK; k++) {
                float xv0 = xs[(size_t)(ty * 4 + 0) * XS_STRIDE + k];
                float xv1 = xs[(size_t)(ty * 4 + 1) * XS_STRIDE + k];
                float xv2 = xs[(size_t)(ty * 4 + 2) * XS_STRIDE + k];
                float xv3 = xs[(size_t)(ty * 4 + 3) * XS_STRIDE + k];
                unsigned long long xd0 = pack2(xv0, xv0);
                unsigned long long xd1 = pack2(xv1, xv1);
                unsigned long long xd2 = pack2(xv2, xv2);
                unsigned long long xd3 = pack2(xv3, xv3);
                const ulonglong2* wr = (const ulonglong2*)(ws + k * E_DIM + tx * 8);
                ulonglong2 wa = wr[0], wb = wr[1];   // 4 expert pairs
                fma2(acc[0][0], xd0, wa.x); fma2(acc[0][1], xd0, wa.y);
                fma2(acc[0][2], xd0, wb.x); fma2(acc[0][3], xd0, wb.y);
                fma2(acc[1][0], xd1, wa.x); fma2(acc[1][1], xd1, wa.y);
                fma2(acc[1][2], xd1, wb.x); fma2(acc[1][3], xd1, wb.y);
                fma2(acc[2][0], xd2, wa.x); fma2(acc[2][1], xd2, wa.y);
                fma2(acc[2][2], xd2, wb.x); fma2(acc[2][3], xd2, wb.y);
                fma2(acc[3][0], xd3, wa.x); fma2(acc[3][1], xd3, wa.y);
                fma2(acc[3][2], xd3, wb.x); fma2(acc[3][3], xd3, wb.y);
            }
        }
        // ---- fold chunk partial into running total (1 fp32 add/lane) ----
#pragma unroll
        for (int r = 0; r < 4; r++)
#pragma unroll
            for (int e = 0; e < 4; e++) { add2(tot[r][e], acc[r][e]); acc[r][e] = 0ULL; }
    }
    __syncthreads();

    // ---- spill biased logits to smem: Ls[row][expert], stride 68 ----
    float* Ls = pool;
#pragma unroll
    for (int r = 0; r < 4; r++) {
        int row = ty * 4 + r;
#pragma unroll
        for (int e = 0; e < 4; e++) {
            int ec = tx * 8 + e * 2;
            float lo = __uint_as_float((unsigned)(tot[r][e] & 0xffffffffULL));
            float hi = __uint_as_float((unsigned)(tot[r][e] >> 32));
            Ls[(size_t)row * LS_STRIDE + ec]     = lo + bsh[ec];
            Ls[(size_t)row * LS_STRIDE + ec + 1] = hi + bsh[ec + 1];
        }
    }
    __syncthreads();

    if (tid < BM) {
        const int row = row0 + tid;
        float* L = Ls + (size_t)tid * LS_STRIDE;
        float mx = L[0];
#pragma unroll
        for (int e = 1; e < E_DIM; e++) mx = fmaxf(mx, L[e]);
        float s = 0.f;
#pragma unroll
        for (int e = 0; e < E_DIM; e++) s += expf(L[e] - mx);
        float inv = 1.f / s;
        // top-8 by raw logits; strict >, lowest index ties (lax.top_k)
        const float NEG_INF = __int_as_float(0xff800000);
        unsigned long long used = 0ULL;
        float gv[TOPK]; int gi[TOPK];
        float gs = 0.f;
#pragma unroll
        for (int j = 0; j < TOPK; j++) {
            float best = NEG_INF; int bi = 0;
            for (int e = 0; e < E_DIM; e++) {
                float v = L[e];
                if (!((used >> e) & 1ULL) && v > best) { best = v; bi = e; }
            }
            used |= (1ULL << bi);
            float g = expf(best - mx) * inv;
            gv[j] = g; gi[j] = bi; gs += g;
            atomicAdd(&hist[bi], 1);
        }
        float rn = 1.f / (gs + 1e-8f);
#pragma unroll
        for (int j = 0; j < TOPK; j++) {
            out_idx[(size_t)row * TOPK + j]  = (float)gi[j];
            out_gate[(size_t)row * TOPK + j] = gv[j] * rn;
        }
    }
    __syncthreads();
    if (tid < E_DIM) atomicAdd(&g_counts[tid], hist[tid]);

    // ---- fused finisher: last CTA computes EMA-usage variance ----
    __syncthreads();
    if (tid == 0) {
        __threadfence();
        int old = atomicAdd(&g_done, 1);
        lastFlag = (old == (int)gridDim.x - 1);
    }
    __syncthreads();
    if (lastFlag && tid == 0) {
        float u[E_DIM];
        float m = 0.f;
        for (int e = 0; e < E_DIM; e++) {
            int c = atomicExch(&g_counts[e], 0);   // read + reset for replay
            u[e] = 0.95f * eu[e] + 0.05f * ((float)c * invN);
            m += u[e];
        }
        m *= (1.f / E_DIM);
        float v = 0.f;
        for (int e = 0; e < E_DIM; e++) {
            float d = u[e] - m;
            v += d * d;
        }
        *out_var = v * (1.f / (E_DIM - 1));   // ddof=1
        atomicExch(&g_done, 0);               // reset for next replay
    }
}

extern "C" void kernel_launch(void* const* d_in, const int* in_sizes, int n_in,
                              void* d_out, int out_size) {
    const float* x  = (const float*)d_in[0];
    const float* W  = (const float*)d_in[1];
    const float* b  = (const float*)d_in[2];
    const float* eu = (const float*)d_in[3];
    const int N = in_sizes[0] / D_DIM;   // 262144

    float* out      = (float*)d_out;
    float* out_idx  = out;                        // [N,8] indices (as float)
    float* out_gate = out + (size_t)N * TOPK;     // [N,8] gates
    float* out_var  = out + (out_size - 1);       // scalar variance

    transpose_w_kernel<<<(E_DIM * D_DIM) / NTHREADS, NTHREADS>>>(W);
    gate_kernel<<<N / BM, NTHREADS>>>(x, b, eu, out_idx, out_gate, out_var,
                                      1.f / (float)N);
}

// round 7
// speedup vs baseline: 1.5837x; 1.0808x over previous
#include <cuda_runtime.h>
#include <math.h>

#define D_DIM   1024
#define E_DIM   64
#define TOPK    8
#define BM      128
#define BK      16
#define NTILES  (D_DIM / BK)          // 64
#define TILES_PER_CHUNK 16            // 256-k chunks (reference-matching)
#define NTHREADS 128
#define XS_STRIDE 17                  // conflict-free x staging/reads
#define WS_STRIDE 80                  // per-k w row: 4 tx-groups at +20 floats
#define TOT_STRIDE 33                 // u64 stride, 2-way max on folds
#define LS_STRIDE 66

// global scratch (allocation-free per harness rules)
__device__ int   g_counts[E_DIM];
__device__ int   g_done;
__device__ float Wt[D_DIM * E_DIM];   // W transposed: Wt[k][e]

__device__ __forceinline__ unsigned long long pack2(float a, float b) {
    unsigned long long r;
    asm("mov.b64 %0, {%1, %2};" : "=l"(r) : "f"(a), "f"(b));
    return r;
}
__device__ __forceinline__ void fma2(unsigned long long& d,
                                     unsigned long long a,
                                     unsigned long long b) {
    // packed 2x fp32 FMA (per-lane IEEE fp32) -- same math as scalar FFMA
    asm("fma.rn.f32x2 %0, %1, %2, %3;" : "=l"(d) : "l"(a), "l"(b), "l"(d));
}
__device__ __forceinline__ void add2(unsigned long long& d,
                                     unsigned long long a) {
    asm("add.rn.f32x2 %0, %0, %1;" : "+l"(d) : "l"(a));
}

// One-shot (per launch) W transpose: read coalesced along k, write [k][e].
__global__ void transpose_w_kernel(const float* __restrict__ W) {
    int idx = blockIdx.x * blockDim.x + threadIdx.x;   // = e*D + k
    int e = idx >> 10, k = idx & (D_DIM - 1);
    Wt[k * E_DIM + e] = W[idx];
}

__global__ __launch_bounds__(NTHREADS, 4)
void gate_kernel(const float* __restrict__ x, const float* __restrict__ b,
                 const float* __restrict__ eu,
                 float* __restrict__ out_idx, float* __restrict__ out_gate,
                 float* __restrict__ out_var, float invN) {
    // pool: xs[128][17] | ws[16][80] | tot/Ls union
    __shared__ __align__(16) float pool[BM * XS_STRIDE + BK * WS_STRIDE
                                        + BM * TOT_STRIDE * 2];
    __shared__ float bsh[E_DIM];
    __shared__ int hist[E_DIM];
    __shared__ int lastFlag;

    float* xs = pool;
    float* ws = pool + BM * XS_STRIDE;
    unsigned long long* totbase =
        (unsigned long long*)(pool + BM * XS_STRIDE + BK * WS_STRIDE);
    float* Ls = pool + BM * XS_STRIDE + BK * WS_STRIDE;   // epilogue alias

    const int tid = threadIdx.x;
    const int tx = tid & 3;      // expert group: experts tx*16 .. tx*16+15
    const int ty = tid >> 2;     // row group:    rows    ty*4 .. ty*4+3
    const int row0 = blockIdx.x * BM;

    if (tid < E_DIM) { bsh[tid] = b[tid]; hist[tid] = 0; }

    unsigned long long acc[4][8];   // [row][expert-pair], current 256-chunk
#pragma unroll
    for (int r = 0; r < 4; r++)
#pragma unroll
        for (int j = 0; j < 8; j++) acc[r][j] = 0ULL;

    unsigned long long* totp = totbase + (size_t)tid * TOT_STRIDE;

    // staging maps
    const int wk  = tid >> 3;          // k-row within tile (0..15)
    const int seg = tid & 7;           // 8-float segment of the 64 experts
    float* wdst = ws + wk * WS_STRIDE + (seg >> 1) * 20 + (seg & 1) * 8;

    float4 xp[4], wp[2];
    // prefetch tile 0
#pragma unroll
    for (int j = 0; j < 4; j++)
        xp[j] = *((const float4*)(x + (size_t)(row0 + tid) * D_DIM) + j);
#pragma unroll
    for (int j = 0; j < 2; j++)
        wp[j] = *((const float4*)(Wt + (size_t)wk * E_DIM + seg * 8) + j);

#pragma unroll 1
    for (int tile = 0; tile < NTILES; tile++) {
        __syncthreads();   // previous tile's consumers done
        // ---- store staged tile (conflict-free patterns) ----
        float* xd = xs + tid * XS_STRIDE;
        xd[0]  = xp[0].x; xd[1]  = xp[0].y; xd[2]  = xp[0].z; xd[3]  = xp[0].w;
        xd[4]  = xp[1].x; xd[5]  = xp[1].y; xd[6]  = xp[1].z; xd[7]  = xp[1].w;
        xd[8]  = xp[2].x; xd[9]  = xp[2].y; xd[10] = xp[2].z; xd[11] = xp[2].w;
        xd[12] = xp[3].x; xd[13] = xp[3].y; xd[14] = xp[3].z; xd[15] = xp[3].w;
        *(float4*)wdst       = wp[0];
        *(float4*)(wdst + 4) = wp[1];
        __syncthreads();
        // ---- prefetch next tile while computing this one ----
        if (tile < NTILES - 1) {
            const int kn = (tile + 1) * BK;
#pragma unroll
            for (int j = 0; j < 4; j++)
                xp[j] = *((const float4*)(x + (size_t)(row0 + tid) * D_DIM + kn) + j);
#pragma unroll
            for (int j = 0; j < 2; j++)
                wp[j] = *((const float4*)(Wt + (size_t)(kn + wk) * E_DIM + seg * 8) + j);
        }
        // ---- mainloop: per k: 4 LDS.32(x) + 4 LDS.128(w) + 32 FFMA2 ----
#pragma unroll
        for (int k = 0; k < BK; k++) {
            float xv0 = xs[(ty * 4 + 0) * XS_STRIDE + k];
            float xv1 = xs[(ty * 4 + 1) * XS_STRIDE + k];
            float xv2 = xs[(ty * 4 + 2) * XS_STRIDE + k];
            float xv3 = xs[(ty * 4 + 3) * XS_STRIDE + k];
            unsigned long long xd0 = pack2(xv0, xv0);
            unsigned long long xd1 = pack2(xv1, xv1);
            unsigned long long xd2 = pack2(xv2, xv2);
            unsigned long long xd3 = pack2(xv3, xv3);
            const ulonglong2* wr =
                (const ulonglong2*)(ws) + (k * 20 + tx * 5);
            ulonglong2 w0 = wr[0], w1 = wr[1], w2 = wr[2], w3 = wr[3];
            fma2(acc[0][0], xd0, w0.x); fma2(acc[0][1], xd0, w0.y);
            fma2(acc[0][2], xd0, w1.x); fma2(acc[0][3], xd0, w1.y);
            fma2(acc[0][4], xd0, w2.x); fma2(acc[0][5], xd0, w2.y);
            fma2(acc[0][6], xd0, w3.x); fma2(acc[0][7], xd0, w3.y);
            fma2(acc[1][0], xd1, w0.x); fma2(acc[1][1], xd1, w0.y);
            fma2(acc[1][2], xd1, w1.x); fma2(acc[1][3], xd1, w1.y);
            fma2(acc[1][4], xd1, w2.x); fma2(acc[1][5], xd1, w2.y);
            fma2(acc[1][6], xd1, w3.x); fma2(acc[1][7], xd1, w3.y);
            fma2(acc[2][0], xd2, w0.x); fma2(acc[2][1], xd2, w0.y);
            fma2(acc[2][2], xd2, w1.x); fma2(acc[2][3], xd2, w1.y);
            fma2(acc[2][4], xd2, w2.x); fma2(acc[2][5], xd2, w2.y);
            fma2(acc[2][6], xd2, w3.x); fma2(acc[2][7], xd2, w3.y);
            fma2(acc[3][0], xd3, w0.x); fma2(acc[3][1], xd3, w0.y);
            fma2(acc[3][2], xd3, w1.x); fma2(acc[3][3], xd3, w1.y);
            fma2(acc[3][4], xd3, w2.x); fma2(acc[3][5], xd3, w2.y);
            fma2(acc[3][6], xd3, w3.x); fma2(acc[3][7], xd3, w3.y);
        }
        // ---- 256-k chunk folds: tot = ((P0+P1)+P2)+P3 (private smem) ----
        if ((tile & (TILES_PER_CHUNK - 1)) == (TILES_PER_CHUNK - 1)) {
            const int ch = tile / TILES_PER_CHUNK;
            if (ch == 0) {
#pragma unroll
                for (int r = 0; r < 4; r++)
#pragma unroll
                    for (int j = 0; j < 8; j++) {
                        totp[r * 8 + j] = acc[r][j];
                        acc[r][j] = 0ULL;
                    }
            } else if (ch < 3) {
#pragma unroll
                for (int r = 0; r < 4; r++)
#pragma unroll
                    for (int j = 0; j < 8; j++) {
                        unsigned long long t = totp[r * 8 + j];
                        add2(t, acc[r][j]);
                        totp[r * 8 + j] = t;
                        acc[r][j] = 0ULL;
                    }
            } else {   // final fold: keep total in registers
#pragma unroll
                for (int r = 0; r < 4; r++)
#pragma unroll
                    for (int j = 0; j < 8; j++) {
                        unsigned long long t = totp[r * 8 + j];
                        add2(t, acc[r][j]);
                        acc[r][j] = t;
                    }
            }
        }
    }
    __syncthreads();   // all tot reads done before Ls overwrites the region

    // ---- spill biased logits: Ls[row][expert], stride 66 ----
#pragma unroll
    for (int r = 0; r < 4; r++) {
        int row = ty * 4 + r;
#pragma unroll
        for (int j = 0; j < 8; j++) {
            int ec = tx * 16 + j * 2;
            float lo = __uint_as_float((unsigned)(acc[r][j] & 0xffffffffULL));
            float hi = __uint_as_float((unsigned)(acc[r][j] >> 32));
            Ls[(size_t)row * LS_STRIDE + ec]     = lo + bsh[ec];
            Ls[(size_t)row * LS_STRIDE + ec + 1] = hi + bsh[ec + 1];
        }
    }
    __syncthreads();

    {
        const int row = row0 + tid;
        float* L = Ls + (size_t)tid * LS_STRIDE;
        float mx = L[0];
#pragma unroll
        for (int e = 1; e < E_DIM; e++) mx = fmaxf(mx, L[e]);
        float s = 0.f;
#pragma unroll
        for (int e = 0; e < E_DIM; e++) s += expf(L[e] - mx);
        float inv = 1.f / s;
        // top-8 by raw logits; strict >, lowest index ties (lax.top_k)
        const float NEG_INF = __int_as_float(0xff800000);
        unsigned long long used = 0ULL;
        float gv[TOPK]; int gi[TOPK];
        float gs = 0.f;
#pragma unroll
        for (int j = 0; j < TOPK; j++) {
            float best = NEG_INF; int bi = 0;
            for (int e = 0; e < E_DIM; e++) {
                float v = L[e];
                if (!((used >> e) & 1ULL) && v > best) { best = v; bi = e; }
            }
            used |= (1ULL << bi);
            float g = expf(best - mx) * inv;
            gv[j] = g; gi[j] = bi; gs += g;
            atomicAdd(&hist[bi], 1);
        }
        float rn = 1.f / (gs + 1e-8f);
#pragma unroll
        for (int j = 0; j < TOPK; j++) {
            out_idx[(size_t)row * TOPK + j]  = (float)gi[j];
            out_gate[(size_t)row * TOPK + j] = gv[j] * rn;
        }
    }
    __syncthreads();
    if (tid < E_DIM) atomicAdd(&g_counts[tid], hist[tid]);

    // ---- fused finisher: last CTA computes EMA-usage variance ----
    __syncthreads();
    if (tid == 0) {
        __threadfence();
        int old = atomicAdd(&g_done, 1);
        lastFlag = (old == (int)gridDim.x - 1);
    }
    __syncthreads();
    if (lastFlag && tid == 0) {
        float u[E_DIM];
        float m = 0.f;
        for (int e = 0; e < E_DIM; e++) {
            int c = atomicExch(&g_counts[e], 0);   // read + reset for replay
            u[e] = 0.95f * eu[e] + 0.05f * ((float)c * invN);
            m += u[e];
        }
        m *= (1.f / E_DIM);
        float v = 0.f;
        for (int e = 0; e < E_DIM; e++) {
            float d = u[e] - m;
            v += d * d;
        }
        *out_var = v * (1.f / (E_DIM - 1));   // ddof=1
        atomicExch(&g_done, 0);               // reset for next replay
    }
}

extern "C" void kernel_launch(void* const* d_in, const int* in_sizes, int n_in,
                              void* d_out, int out_size) {
    const float* x  = (const float*)d_in[0];
    const float* W  = (const float*)d_in[1];
    const float* b  = (const float*)d_in[2];
    const float* eu = (const float*)d_in[3];
    const int N = in_sizes[0] / D_DIM;   // 262144

    float* out      = (float*)d_out;
    float* out_idx  = out;                        // [N,8] indices (as float)
    float* out_gate = out + (size_t)N * TOPK;     // [N,8] gates
    float* out_var  = out + (out_size - 1);       // scalar variance

    transpose_w_kernel<<<(E_DIM * D_DIM) / 256, 256>>>(W);
    gate_kernel<<<N / BM, NTHREADS>>>(x, b, eu, out_idx, out_gate, out_var,
                                      1.f / (float)N);
}

// round 8
// speedup vs baseline: 2.1124x; 1.3338x over previous
#include <cuda_runtime.h>
#include <math.h>

#define D_DIM   1024
#define E_DIM   64
#define TOPK    8
#define BM      256
#define BK      8
#define NTILES  (D_DIM / BK)          // 128
#define TILES_PER_CHUNK 32            // 256-k chunks (reference-matching)
#define NTHREADS 128
#define XS_KSTRIDE 320                // 256 rows + (row>>2) pad
#define WS_KSTRIDE 80                 // 4 expert-groups at +20 floats
#define TOT_USTRIDE 65                // u64 stride per thread
// dynamic smem float offsets
#define WS_OFF  (BK * XS_KSTRIDE)                  // 2560
#define TOT_OFF (WS_OFF + BK * WS_KSTRIDE)         // 3200 (8B-aligned: 12800)
#define SMEM_FLOATS (TOT_OFF + NTHREADS * TOT_USTRIDE * 2)   // 19840
#define LS_STRIDE 66                               // epilogue overlay stride

// global scratch (allocation-free per harness rules)
__device__ int   g_counts[E_DIM];
__device__ int   g_done;
__device__ float Wt[D_DIM * E_DIM];   // W transposed: Wt[k][e]

__device__ __forceinline__ unsigned long long pack2(float a, float b) {
    unsigned long long r;
    asm("mov.b64 %0, {%1, %2};" : "=l"(r) : "f"(a), "f"(b));
    return r;
}
__device__ __forceinline__ void fma2(unsigned long long& d,
                                     unsigned long long a,
                                     unsigned long long b) {
    // packed 2x fp32 FMA (per-lane IEEE fp32) -- same math as scalar FFMA
    asm("fma.rn.f32x2 %0, %1, %2, %3;" : "=l"(d) : "l"(a), "l"(b), "l"(d));
}
__device__ __forceinline__ void add2(unsigned long long& d,
                                     unsigned long long a) {
    asm("add.rn.f32x2 %0, %0, %1;" : "+l"(d) : "l"(a));
}

// One-shot (per launch) W transpose: read coalesced along k, write [k][e].
__global__ void transpose_w_kernel(const float* __restrict__ W) {
    int idx = blockIdx.x * blockDim.x + threadIdx.x;   // = e*D + k
    int e = idx >> 10, k = idx & (D_DIM - 1);
    Wt[k * E_DIM + e] = W[idx];
}

__global__ __launch_bounds__(NTHREADS, 2)
void gate_kernel(const float* __restrict__ x, const float* __restrict__ b,
                 const float* __restrict__ eu,
                 float* __restrict__ out_idx, float* __restrict__ out_gate,
                 float* __restrict__ out_var, float invN) {
    extern __shared__ __align__(16) float pool[];
    __shared__ float bsh[E_DIM];
    __shared__ int hist[E_DIM];
    __shared__ int lastFlag;

    float* xs = pool;                                 // [BK][XS_KSTRIDE]
    float* ws = pool + WS_OFF;                        // [BK][WS_KSTRIDE]
    unsigned long long* tot = (unsigned long long*)(pool + TOT_OFF);
    float* Ls = pool;                                 // epilogue overlay

    const int tid = threadIdx.x;
    const int tx = tid & 3;       // experts tx*16 .. tx*16+15
    const int ty = tid >> 2;      // rows    ty*8  .. ty*8+7
    const int row0 = blockIdx.x * BM;

    if (tid < E_DIM) { bsh[tid] = b[tid]; hist[tid] = 0; }

    unsigned long long acc[8][8];   // [row][expert-pair] current 256-chunk
#pragma unroll
    for (int r = 0; r < 8; r++)
#pragma unroll
        for (int j = 0; j < 8; j++) acc[r][j] = 0ULL;

    unsigned long long* totp = tot + (size_t)tid * TOT_USTRIDE;

    // staging maps
    const int pa = tid + (tid >> 2);                      // phys row of tid
    const int pb = pa + 160;                              // phys of tid+128
    const int wk = tid >> 4;                              // w k-row
    const int wg = (tid >> 2) & 3;                        // expert group
    const int wr_ = (tid & 3) << 2;                       // within group
    float* wdst = ws + wk * WS_KSTRIDE + wg * 20 + wr_;

    const float* xaL = x + (size_t)(row0 + tid) * D_DIM;
    const float* xaH = x + (size_t)(row0 + 128 + tid) * D_DIM;

    float4 xp[4], wp;
    // prefetch tile 0
    xp[0] = *(const float4*)(xaL);
    xp[1] = *(const float4*)(xaL + 4);
    xp[2] = *(const float4*)(xaH);
    xp[3] = *(const float4*)(xaH + 4);
    wp    = *((const float4*)Wt + tid);

#pragma unroll 1
    for (int tile = 0; tile < NTILES; tile++) {
        __syncthreads();   // previous tile's consumers done
        // ---- store staged tile ----
        xs[0 * XS_KSTRIDE + pa] = xp[0].x;  xs[1 * XS_KSTRIDE + pa] = xp[0].y;
        xs[2 * XS_KSTRIDE + pa] = xp[0].z;  xs[3 * XS_KSTRIDE + pa] = xp[0].w;
        xs[4 * XS_KSTRIDE + pa] = xp[1].x;  xs[5 * XS_KSTRIDE + pa] = xp[1].y;
        xs[6 * XS_KSTRIDE + pa] = xp[1].z;  xs[7 * XS_KSTRIDE + pa] = xp[1].w;
        xs[0 * XS_KSTRIDE + pb] = xp[2].x;  xs[1 * XS_KSTRIDE + pb] = xp[2].y;
        xs[2 * XS_KSTRIDE + pb] = xp[2].z;  xs[3 * XS_KSTRIDE + pb] = xp[2].w;
        xs[4 * XS_KSTRIDE + pb] = xp[3].x;  xs[5 * XS_KSTRIDE + pb] = xp[3].y;
        xs[6 * XS_KSTRIDE + pb] = xp[3].z;  xs[7 * XS_KSTRIDE + pb] = xp[3].w;
        *(float4*)wdst = wp;
        __syncthreads();
        // ---- prefetch next tile ----
        if (tile < NTILES - 1) {
            const int kn = (tile + 1) * BK;
            xp[0] = *(const float4*)(xaL + kn);
            xp[1] = *(const float4*)(xaL + kn + 4);
            xp[2] = *(const float4*)(xaH + kn);
            xp[3] = *(const float4*)(xaH + kn + 4);
            wp    = *((const float4*)(Wt + (size_t)kn * E_DIM) + tid);
        }
        // ---- compute: per k: 8 LDS.32(x) + 2 LDS.128(w) + 64 FFMA2 ----
#pragma unroll
        for (int k = 0; k < BK; k++) {
            const float* xb = xs + k * XS_KSTRIDE + 10 * ty;
            const ulonglong2* wrp =
                (const ulonglong2*)(ws + k * WS_KSTRIDE + tx * 20);
            ulonglong2 w0 = wrp[0], w1 = wrp[1];
            ulonglong2 w2 = *(const ulonglong2*)((const unsigned long long*)
                            (ws + k * WS_KSTRIDE + tx * 20 + 8));
            ulonglong2 w3 = *(const ulonglong2*)((const unsigned long long*)
                            (ws + k * WS_KSTRIDE + tx * 20 + 8) + 2);
            float xv;
            unsigned long long xd;
#pragma unroll
            for (int r = 0; r < 8; r++) {
                xv = xb[r + (r >> 2)];
                xd = pack2(xv, xv);
                fma2(acc[r][0], xd, w0.x); fma2(acc[r][1], xd, w0.y);
                fma2(acc[r][2], xd, w1.x); fma2(acc[r][3], xd, w1.y);
                fma2(acc[r][4], xd, w2.x); fma2(acc[r][5], xd, w2.y);
                fma2(acc[r][6], xd, w3.x); fma2(acc[r][7], xd, w3.y);
            }
        }
        // ---- 256-k chunk folds: tot = ((P0+P1)+P2)+P3 ----
        if ((tile & (TILES_PER_CHUNK - 1)) == (TILES_PER_CHUNK - 1)) {
            const int ch = tile / TILES_PER_CHUNK;
            if (ch == 0) {
#pragma unroll
                for (int r = 0; r < 8; r++)
#pragma unroll
                    for (int j = 0; j < 8; j++) {
                        totp[r * 8 + j] = acc[r][j];
                        acc[r][j] = 0ULL;
                    }
            } else if (ch < 3) {
#pragma unroll
                for (int r = 0; r < 8; r++)
#pragma unroll
                    for (int j = 0; j < 8; j++) {
                        unsigned long long t = totp[r * 8 + j];
                        add2(t, acc[r][j]);
                        totp[r * 8 + j] = t;
                        acc[r][j] = 0ULL;
                    }
            } else {   // final fold: keep total in registers
#pragma unroll
                for (int r = 0; r < 8; r++)
#pragma unroll
                    for (int j = 0; j < 8; j++) {
                        unsigned long long t = totp[r * 8 + j];
                        add2(t, acc[r][j]);
                        acc[r][j] = t;
                    }
            }
        }
    }
    __syncthreads();   // tot region dead; Ls may overlay pool

    // ---- spill biased logits: Ls[row][expert], stride 66 ----
#pragma unroll
    for (int r = 0; r < 8; r++) {
        int row = ty * 8 + r;
#pragma unroll
        for (int j = 0; j < 8; j++) {
            int ec = tx * 16 + j * 2;
            float lo = __uint_as_float((unsigned)(acc[r][j] & 0xffffffffULL));
            float hi = __uint_as_float((unsigned)(acc[r][j] >> 32));
            Ls[(size_t)row * LS_STRIDE + ec]     = lo + bsh[ec];
            Ls[(size_t)row * LS_STRIDE + ec + 1] = hi + bsh[ec + 1];
        }
    }
    __syncthreads();

#pragma unroll 1
    for (int half = 0; half < 2; half++) {
        const int lrow = tid + half * 128;
        const int row = row0 + lrow;
        float* L = Ls + (size_t)lrow * LS_STRIDE;
        float mx = L[0];
#pragma unroll
        for (int e = 1; e < E_DIM; e++) mx = fmaxf(mx, L[e]);
        float s = 0.f;
#pragma unroll
        for (int e = 0; e < E_DIM; e++) s += expf(L[e] - mx);
        float inv = 1.f / s;
        // top-8 by raw logits; strict >, lowest index ties (lax.top_k)
        const float NEG_INF = __int_as_float(0xff800000);
        unsigned long long used = 0ULL;
        float gv[TOPK]; int gi[TOPK];
        float gs = 0.f;
#pragma unroll
        for (int j = 0; j < TOPK; j++) {
            float best = NEG_INF; int bi = 0;
            for (int e = 0; e < E_DIM; e++) {
                float v = L[e];
                if (!((used >> e) & 1ULL) && v > best) { best = v; bi = e; }
            }
            used |= (1ULL << bi);
            float g = expf(best - mx) * inv;
            gv[j] = g; gi[j] = bi; gs += g;
            atomicAdd(&hist[bi], 1);
        }
        float rn = 1.f / (gs + 1e-8f);
#pragma unroll
        for (int j = 0; j < TOPK; j++) {
            out_idx[(size_t)row * TOPK + j]  = (float)gi[j];
            out_gate[(size_t)row * TOPK + j] = gv[j] * rn;
        }
    }
    __syncthreads();
    if (tid < E_DIM) atomicAdd(&g_counts[tid], hist[tid]);

    // ---- fused finisher: last CTA computes EMA-usage variance ----
    __syncthreads();
    if (tid == 0) {
        __threadfence();
        int old = atomicAdd(&g_done, 1);
        lastFlag = (old == (int)gridDim.x - 1);
    }
    __syncthreads();
    if (lastFlag && tid == 0) {
        float u[E_DIM];
        float m = 0.f;
        for (int e = 0; e < E_DIM; e++) {
            int c = atomicExch(&g_counts[e], 0);   // read + reset for replay
            u[e] = 0.95f * eu[e] + 0.05f * ((float)c * invN);
            m += u[e];
        }
        m *= (1.f / E_DIM);
        float v = 0.f;
        for (int e = 0; e < E_DIM; e++) {
            float d = u[e] - m;
            v += d * d;
        }
        *out_var = v * (1.f / (E_DIM - 1));   // ddof=1
        atomicExch(&g_done, 0);               // reset for next replay
    }
}

extern "C" void kernel_launch(void* const* d_in, const int* in_sizes, int n_in,
                              void* d_out, int out_size) {
    const float* x  = (const float*)d_in[0];
    const float* W  = (const float*)d_in[1];
    const float* b  = (const float*)d_in[2];
    const float* eu = (const float*)d_in[3];
    const int N = in_sizes[0] / D_DIM;   // 262144

    float* out      = (float*)d_out;
    float* out_idx  = out;                        // [N,8] indices (as float)
    float* out_gate = out + (size_t)N * TOPK;     // [N,8] gates
    float* out_var  = out + (out_size - 1);       // scalar variance

    static int smem_set = 0;
    if (!smem_set) {
        cudaFuncSetAttribute(gate_kernel,
                             cudaFuncAttributeMaxDynamicSharedMemorySize,
                             SMEM_FLOATS * 4);
        smem_set = 1;
    }

    transpose_w_kernel<<<(E_DIM * D_DIM) / 256, 256>>>(W);
    gate_kernel<<<N / BM, NTHREADS, SMEM_FLOATS * 4>>>(
        x, b, eu, out_idx, out_gate, out_var, 1.f / (float)N);
}